// round 13
// baseline (speedup 1.0000x reference)
#include <cuda_runtime.h>
#include <cstdint>

#define KN 32
#define DF 128
#define RP 132   // DQ row pad: 132 mod 32 = 4 -> conflict-free frag/m-phase maps, 16B rows
#define LP 36    // L row pad: float2/float4 aligned, col reads conflict-free

// smem floats: DQ 64*RP=8448 | L 32*LP=1152 | stats 384 | mbar 4 -> 39952 B, 5 CTAs/SM
#define SMEM_FLOATS (64 * RP + KN * LP + 384 + 4)
#define SMEM_BYTES  (SMEM_FLOATS * 4)

__device__ __forceinline__ unsigned bfpack(float e0, float e1) {
    unsigned r; asm("cvt.rn.bf16x2.f32 %0, %1, %2;" : "=r"(r) : "f"(e1), "f"(e0)); return r;
}
__device__ __forceinline__ void bfsplit(float e0, float e1, unsigned& hi, unsigned& lo) {
    hi = bfpack(e0, e1);
    float h0 = __uint_as_float(hi << 16);
    float h1 = __uint_as_float(hi & 0xFFFF0000u);
    lo = bfpack(e0 - h0, e1 - h1);
}
__device__ __forceinline__ void mma16(float* c, const unsigned* a, const unsigned* b) {
    asm volatile("mma.sync.aligned.m16n8k16.row.col.f32.bf16.bf16.f32 "
        "{%0,%1,%2,%3}, {%4,%5,%6,%7}, {%8,%9}, {%0,%1,%2,%3};"
        : "+f"(c[0]), "+f"(c[1]), "+f"(c[2]), "+f"(c[3])
        : "r"(a[0]), "r"(a[1]), "r"(a[2]), "r"(a[3]), "r"(b[0]), "r"(b[1]));
}

__global__ void __launch_bounds__(256, 5)
coatt_mma(const float* __restrict__ feat,
          const int* __restrict__ sim_idx,
          const int* __restrict__ cor_idx,
          float* __restrict__ out)
{
    extern __shared__ float sh[];
    float* DQ    = sh;                     // [64][RP] rows 0-31 Dm, 32-63 Qm
    float* L     = sh + 64 * RP;           // [32][LP]; later: sm0 [384] | sm1 [384]
    float* stats = L + KN * LP;
    float* Mc = stats;                     // col max      -> later Wv
    float* Ci = stats + 32;                // 1/(32*csum)  -> later Pv
    float* Mr = stats + 64;                // row max      -> later Vv
    float* Rs = stats + 96;                // row sum
    float* Wp = stats + 128;               // [8][32] w partials; reused as v partials
    const uint32_t mbar =
        (uint32_t)__cvta_generic_to_shared(stats + 384);

    const int tid  = threadIdx.x;
    const int q    = tid >> 5;             // warp 0..7
    const int lane = tid & 31;
    const int mh   = q >> 2;               // m-half: rows [16mh, 16mh+16)
    const int nh   = (q >> 1) & 1;         // n-half: cols [16nh, 16nh+16)
    const int dh   = q & 1;                // d-half: k in [64dh, 64dh+64)
    const size_t node = blockIdx.x;

    // ---- early residual prefetch ----
    float res = 0.f;
    if (tid < DF) res = __ldg(feat + node * DF + tid);

    // ---- gather via TMA bulk copies: row r (0..63) = one contiguous 512B ----
    if (tid == 0)
        asm volatile("mbarrier.init.shared.b64 [%0], 64;" :: "r"(mbar) : "memory");
    __syncthreads();

    if (tid < 64) {
        const int ridx = (tid < KN) ? __ldg(sim_idx + node * KN + tid)
                                    : __ldg(cor_idx + node * KN + tid - KN);
        const float* src = feat + (size_t)ridx * DF;
        const uint32_t dst = (uint32_t)__cvta_generic_to_shared(DQ + tid * RP);
        asm volatile("mbarrier.arrive.expect_tx.shared.b64 _, [%0], 512;"
                     :: "r"(mbar) : "memory");
        asm volatile("cp.async.bulk.shared::cluster.global.mbarrier::complete_tx::bytes "
                     "[%0], [%1], 512, [%2];"
                     :: "r"(dst), "l"(src), "r"(mbar) : "memory");
    }
    asm volatile(
        "{\n\t.reg .pred P1;\n\t"
        "WL%=:\n\t"
        "mbarrier.try_wait.parity.acquire.cta.shared::cta.b64 P1, [%0], 0, 0x989680;\n\t"
        "@P1 bra.uni WD%=;\n\t"
        "bra.uni WL%=;\n\t"
        "WD%=:\n\t}"
        :: "r"(mbar) : "memory");
    __syncthreads();

    // ---- L partial: warp q computes m16 x n16 x k64 (split-bf16, 3-term) ----
    float C[2][4];
    #pragma unroll
    for (int ni = 0; ni < 2; ni++)
        #pragma unroll
        for (int e = 0; e < 4; e++) C[ni][e] = 0.f;

    const int r8 = lane >> 2;              // 0..7
    const int c4 = lane & 3;               // 0..3
    #pragma unroll
    for (int kt = 0; kt < 4; kt++) {
        const int d0 = 64 * dh + 16 * kt;
        unsigned ah[4], al[4];
        {
            const float* base = DQ + (16 * mh + r8) * RP + d0 + 2 * c4;
            float2 p0 = *(const float2*)(base);
            float2 p1 = *(const float2*)(base + 8 * RP);
            float2 p2 = *(const float2*)(base + 8);
            float2 p3 = *(const float2*)(base + 8 * RP + 8);
            bfsplit(p0.x, p0.y, ah[0], al[0]);
            bfsplit(p1.x, p1.y, ah[1], al[1]);
            bfsplit(p2.x, p2.y, ah[2], al[2]);
            bfsplit(p3.x, p3.y, ah[3], al[3]);
        }
        unsigned bh[2][2], bl[2][2];
        #pragma unroll
        for (int ni = 0; ni < 2; ni++) {
            const float* base = DQ + (32 + 16 * nh + 8 * ni + r8) * RP + d0 + 2 * c4;
            float2 p0 = *(const float2*)(base);
            float2 p1 = *(const float2*)(base + 8);
            bfsplit(p0.x, p0.y, bh[ni][0], bl[ni][0]);
            bfsplit(p1.x, p1.y, bh[ni][1], bl[ni][1]);
        }
        #pragma unroll
        for (int ni = 0; ni < 2; ni++) {
            mma16(C[ni], al, bh[ni]);
            mma16(C[ni], ah, bl[ni]);
            mma16(C[ni], ah, bh[ni]);
        }
    }

    // ---- merge d-halves: dh0 stores, dh1 adds (4 disjoint (mh,nh) tiles concurrent) ----
    if (dh == 0) {
        #pragma unroll
        for (int ni = 0; ni < 2; ni++) {
            const int row = 16 * mh + r8;
            const int col = 16 * nh + 8 * ni + 2 * c4;
            *(float2*)(L + row * LP + col)       = make_float2(C[ni][0], C[ni][1]);
            *(float2*)(L + (row + 8) * LP + col) = make_float2(C[ni][2], C[ni][3]);
        }
    }
    __syncthreads();
    if (dh == 1) {
        #pragma unroll
        for (int ni = 0; ni < 2; ni++) {
            const int row = 16 * mh + r8;
            const int col = 16 * nh + 8 * ni + 2 * c4;
            float2 t0 = *(float2*)(L + row * LP + col);
            float2 t1 = *(float2*)(L + (row + 8) * LP + col);
            t0.x += C[ni][0]; t0.y += C[ni][1];
            t1.x += C[ni][2]; t1.y += C[ni][3];
            *(float2*)(L + row * LP + col)       = t0;
            *(float2*)(L + (row + 8) * LP + col) = t1;
        }
    }
    __syncthreads();

    // ---- stats: warp0 col max/sum (scalar), warp1 row max/sum (rotated float4) ----
    if (q == 0) {
        const int j = lane;
        float mc = -1e30f;
        #pragma unroll
        for (int k = 0; k < KN; k++) mc = fmaxf(mc, L[k * LP + j]);
        float cs = 0.f;
        #pragma unroll
        for (int k = 0; k < KN; k++) cs += __expf(L[k * LP + j] - mc);
        Mc[j] = mc;
        Ci[j] = 1.0f / (32.0f * cs);
    } else if (q == 1) {
        const int k = lane;
        const float* ra = L + k * LP;
        float mr = -1e30f;
        #pragma unroll
        for (int i = 0; i < 8; i++) {
            const int cc = 4 * ((i + (k >> 3)) & 7);
            float4 v = *(const float4*)(ra + cc);
            mr = fmaxf(mr, fmaxf(fmaxf(v.x, v.y), fmaxf(v.z, v.w)));
        }
        float rs = 0.f;
        #pragma unroll
        for (int i = 0; i < 8; i++) {
            const int cc = 4 * ((i + (k >> 3)) & 7);
            float4 v = *(const float4*)(ra + cc);
            rs += __expf(v.x - mr) + __expf(v.y - mr) + __expf(v.z - mr) + __expf(v.w - mr);
        }
        Mr[k] = mr;
        Rs[k] = rs;
    }
    __syncthreads();

    // ---- w partials: 8 warps, 4-k rotated chunks (conflict-free rows) ----
    {
        const int j  = lane;
        const int k0 = 4 * ((q + (j >> 3)) & 7);
        const float* pa = L + j * LP + k0;
        float wj;
        wj  = __expf(pa[0] - Mc[k0 + 0]) * Ci[k0 + 0];
        wj += __expf(pa[1] - Mc[k0 + 1]) * Ci[k0 + 1];
        wj += __expf(pa[2] - Mc[k0 + 2]) * Ci[k0 + 2];
        wj += __expf(pa[3] - Mc[k0 + 3]) * Ci[k0 + 3];
        Wp[q * 32 + j] = wj;
    }
    __syncthreads();

    // ---- Wv/Pv reduce (warp0) ----
    if (tid < 32) {
        const int j = tid;
        float wv = ((Wp[j] + Wp[32 + j]) + (Wp[64 + j] + Wp[96 + j]))
                 + ((Wp[128 + j] + Wp[160 + j]) + (Wp[192 + j] + Wp[224 + j]));
        Mc[j] = wv;                        // Wv
        Ci[j] = __fdividef(wv, Rs[j]);     // Pv
    }
    __syncthreads();

    // ---- v partials: warp q, k in [4q,4q+4), column reads; Wp reused ----
    {
        const int j = lane;
        float vj = 0.f;
        #pragma unroll
        for (int i = 0; i < 4; i++) {
            const int k = 4 * q + i;
            vj += Ci[k] * __expf(L[k * LP + j] - Mr[k]);
        }
        Wp[q * 32 + j] = vj;
    }
    __syncthreads();

    // ---- Vv reduce (warp0) into Mr (dead) ----
    if (tid < 32) {
        const int j = tid;
        Mr[j] = ((Wp[j] + Wp[32 + j]) + (Wp[64 + j] + Wp[96 + j]))
              + ((Wp[128 + j] + Wp[160 + j]) + (Wp[192 + j] + Wp[224 + j]));   // Vv
    }
    __syncthreads();

    // ---- m partials: thread-half jh covers j in [16jh,16jh+16) ----
    {
        const int jh = tid >> 7;           // 0/1
        const int d  = tid & 127;
        const int j0 = 16 * jh;
        float m1 = 0.f, m2 = 0.f, m3 = 0.f;
        #pragma unroll
        for (int i = 0; i < 16; i++) {
            const int j = j0 + i;
            float dd = DQ[j * RP + d];
            float qq = DQ[(32 + j) * RP + d];
            m1 += qq;
            m2 += Mc[j] * dd;     // Wv
            m3 += Mr[j] * qq;     // Vv
        }
        float* smp = L + jh * 384;         // sm0 | sm1 (L dead)
        smp[d]       = m1 * (1.0f / 32.0f);
        smp[128 + d] = m2;
        smp[256 + d] = m3;
    }
    __syncthreads();

    // ---- combine halves + AvgPool1d(3,3) + residual ----
    if (tid < DF) {
        const int g = tid;
        float h = ((L[3 * g]     + L[384 + 3 * g])
                 + (L[3 * g + 1] + L[384 + 3 * g + 1])
                 + (L[3 * g + 2] + L[384 + 3 * g + 2])) * (1.0f / 3.0f);
        out[node * DF + g] = res + h;
    }
}

extern "C" void kernel_launch(void* const* d_in, const int* in_sizes, int n_in,
                              void* d_out, int out_size)
{
    const float* feat = (const float*)d_in[0];
    const int*   sim  = (const int*)d_in[1];
    const int*   cor  = (const int*)d_in[2];
    float*       out  = (float*)d_out;

    const int n_nodes = in_sizes[1] / KN;    // 20000
    cudaFuncSetAttribute(coatt_mma, cudaFuncAttributeMaxDynamicSharedMemorySize, SMEM_BYTES);
    coatt_mma<<<n_nodes, 256, SMEM_BYTES>>>(feat, sim, cor, out);
}

// round 14
// speedup vs baseline: 1.0821x; 1.0821x over previous
#include <cuda_runtime.h>
#include <cstdint>

#define KN 32
#define DF 128
#define RP 132   // DQ row pad: 132 mod 32 = 4 -> conflict-free frag/m-phase maps, 16B rows
#define LP 36    // Lp partial-row pad: float2 aligned

// smem floats: DQ 8448 | Lp 1152 (later sm 768) | comb 192 | WvVv 64 | mbar 4 -> 39440 B, 5 CTAs/SM
#define SMEM_FLOATS (64 * RP + KN * LP + 192 + 64 + 4)
#define SMEM_BYTES  (SMEM_FLOATS * 4)

__device__ __forceinline__ unsigned bfpack(float e0, float e1) {
    unsigned r; asm("cvt.rn.bf16x2.f32 %0, %1, %2;" : "=r"(r) : "f"(e1), "f"(e0)); return r;
}
__device__ __forceinline__ void bfsplit(float e0, float e1, unsigned& hi, unsigned& lo) {
    hi = bfpack(e0, e1);
    float h0 = __uint_as_float(hi << 16);
    float h1 = __uint_as_float(hi & 0xFFFF0000u);
    lo = bfpack(e0 - h0, e1 - h1);
}
__device__ __forceinline__ void mma16(float* c, const unsigned* a, const unsigned* b) {
    asm volatile("mma.sync.aligned.m16n8k16.row.col.f32.bf16.bf16.f32 "
        "{%0,%1,%2,%3}, {%4,%5,%6,%7}, {%8,%9}, {%0,%1,%2,%3};"
        : "+f"(c[0]), "+f"(c[1]), "+f"(c[2]), "+f"(c[3])
        : "r"(a[0]), "r"(a[1]), "r"(a[2]), "r"(a[3]), "r"(b[0]), "r"(b[1]));
}
__device__ __forceinline__ float bxmax(float x, int m) {
    return fmaxf(x, __shfl_xor_sync(0xffffffffu, x, m));
}
__device__ __forceinline__ float bxsum(float x, int m) {
    return x + __shfl_xor_sync(0xffffffffu, x, m);
}

__global__ void __launch_bounds__(128, 5)
coatt_mma(const float* __restrict__ feat,
          const int* __restrict__ sim_idx,
          const int* __restrict__ cor_idx,
          float* __restrict__ out)
{
    extern __shared__ float sh[];
    float* DQ  = sh;                       // [64][RP] rows 0-31 Dm, 32-63 Qm
    float* Lp  = sh + 64 * RP;             // [32][LP] dh=0 partials; later sm[768]
    float* RM  = Lp + KN * LP;             // [2][32] rowmax partials
    float* WPc = RM + 64;                  // [2][32] w partials
    float* RSc = WPc + 64;                 // [2][32] rowsum partials
    float* Wv  = RSc + 64;                 // [32]
    float* Vv  = Wv + 32;                  // [32]
    float* sm  = Lp;                       // alias (epilogue)
    const uint32_t mbar = (uint32_t)__cvta_generic_to_shared(Vv + 32);

    const int tid  = threadIdx.x;
    const int q    = tid >> 5;
    const int lane = tid & 31;
    const int nh   = q >> 1;               // cols [16nh, 16nh+16)
    const int dh   = q & 1;                // k in [64dh, 64dh+64)
    const size_t node = blockIdx.x;

    // ---- early residual prefetch ----
    const float res = __ldg(feat + node * DF + tid);

    // ---- gather via TMA bulk copies: row r (0..63) = contiguous 512B ----
    if (tid == 0)
        asm volatile("mbarrier.init.shared.b64 [%0], 64;" :: "r"(mbar) : "memory");
    __syncthreads();
    if (tid < 64) {
        const int ridx = (tid < KN) ? __ldg(sim_idx + node * KN + tid)
                                    : __ldg(cor_idx + node * KN + tid - KN);
        const float* src = feat + (size_t)ridx * DF;
        const uint32_t dst = (uint32_t)__cvta_generic_to_shared(DQ + tid * RP);
        asm volatile("mbarrier.arrive.expect_tx.shared.b64 _, [%0], 512;"
                     :: "r"(mbar) : "memory");
        asm volatile("cp.async.bulk.shared::cluster.global.mbarrier::complete_tx::bytes "
                     "[%0], [%1], 512, [%2];"
                     :: "r"(dst), "l"(src), "r"(mbar) : "memory");
    }
    asm volatile(
        "{\n\t.reg .pred P1;\n\t"
        "WL%=:\n\t"
        "mbarrier.try_wait.parity.acquire.cta.shared::cta.b64 P1, [%0], 0, 0x989680;\n\t"
        "@P1 bra.uni WD%=;\n\t"
        "bra.uni WL%=;\n\t"
        "WD%=:\n\t}"
        :: "r"(mbar) : "memory");
    __syncthreads();

    // ---- L partial via split-bf16 3-term mma: warp q = (nh, dh), m32 n16 k64 ----
    float C[2][2][4];
    #pragma unroll
    for (int mi = 0; mi < 2; mi++)
        #pragma unroll
        for (int ni = 0; ni < 2; ni++)
            #pragma unroll
            for (int e = 0; e < 4; e++) C[mi][ni][e] = 0.f;

    const int r8 = lane >> 2;
    const int c4 = lane & 3;
    #pragma unroll
    for (int kt = 0; kt < 4; kt++) {
        const int d0 = 64 * dh + 16 * kt;
        unsigned ah[2][4], al[2][4];
        #pragma unroll
        for (int mi = 0; mi < 2; mi++) {
            const float* base = DQ + (16 * mi + r8) * RP + d0 + 2 * c4;
            float2 p0 = *(const float2*)(base);
            float2 p1 = *(const float2*)(base + 8 * RP);
            float2 p2 = *(const float2*)(base + 8);
            float2 p3 = *(const float2*)(base + 8 * RP + 8);
            bfsplit(p0.x, p0.y, ah[mi][0], al[mi][0]);
            bfsplit(p1.x, p1.y, ah[mi][1], al[mi][1]);
            bfsplit(p2.x, p2.y, ah[mi][2], al[mi][2]);
            bfsplit(p3.x, p3.y, ah[mi][3], al[mi][3]);
        }
        unsigned bh[2][2], bl[2][2];
        #pragma unroll
        for (int ni = 0; ni < 2; ni++) {
            const float* base = DQ + (32 + 16 * nh + 8 * ni + r8) * RP + d0 + 2 * c4;
            float2 p0 = *(const float2*)(base);
            float2 p1 = *(const float2*)(base + 8);
            bfsplit(p0.x, p0.y, bh[ni][0], bl[ni][0]);
            bfsplit(p1.x, p1.y, bh[ni][1], bl[ni][1]);
        }
        #pragma unroll
        for (int mi = 0; mi < 2; mi++)
            #pragma unroll
            for (int ni = 0; ni < 2; ni++) {
                mma16(C[mi][ni], al[mi], bh[ni]);
                mma16(C[mi][ni], ah[mi], bl[ni]);
                mma16(C[mi][ni], ah[mi], bh[ni]);
            }
    }

    // ---- dh=0 warps store partials; dh=1 warps absorb into registers ----
    if (dh == 0) {
        #pragma unroll
        for (int mi = 0; mi < 2; mi++)
            #pragma unroll
            for (int ni = 0; ni < 2; ni++) {
                const int row = 16 * mi + r8;
                const int col = 16 * nh + 8 * ni + 2 * c4;
                *(float2*)(Lp + row * LP + col)       = make_float2(C[mi][ni][0], C[mi][ni][1]);
                *(float2*)(Lp + (row + 8) * LP + col) = make_float2(C[mi][ni][2], C[mi][ni][3]);
            }
    }
    __syncthreads();

    if (dh == 1) {
        // absorb partials: final L now register-resident in warps q1/q3
        #pragma unroll
        for (int mi = 0; mi < 2; mi++)
            #pragma unroll
            for (int ni = 0; ni < 2; ni++) {
                const int row = 16 * mi + r8;
                const int col = 16 * nh + 8 * ni + 2 * c4;
                float2 t0 = *(float2*)(Lp + row * LP + col);
                float2 t1 = *(float2*)(Lp + (row + 8) * LP + col);
                C[mi][ni][0] += t0.x; C[mi][ni][1] += t0.y;
                C[mi][ni][2] += t1.x; C[mi][ni][3] += t1.y;
            }
        // thread holds rows {r8, r8+8, r8+16, r8+24} x cols {8ni+2c4+par} (+16nh)
        // ---- col stats: reduce over rows = in-thread (mi,eh) + bfly over r8 (4,8,16)
        float cm[2][2], civ[2][2];
        #pragma unroll
        for (int ni = 0; ni < 2; ni++)
            #pragma unroll
            for (int par = 0; par < 2; par++) {
                float m = fmaxf(fmaxf(C[0][ni][par], C[0][ni][par + 2]),
                                fmaxf(C[1][ni][par], C[1][ni][par + 2]));
                m = bxmax(m, 4); m = bxmax(m, 8); m = bxmax(m, 16);
                cm[ni][par] = m;
            }
        float E[2][2][4];
        #pragma unroll
        for (int mi = 0; mi < 2; mi++)
            #pragma unroll
            for (int ni = 0; ni < 2; ni++)
                #pragma unroll
                for (int e = 0; e < 4; e++)
                    E[mi][ni][e] = __expf(C[mi][ni][e] - cm[ni][e & 1]);
        #pragma unroll
        for (int ni = 0; ni < 2; ni++)
            #pragma unroll
            for (int par = 0; par < 2; par++) {
                float s = (E[0][ni][par] + E[0][ni][par + 2])
                        + (E[1][ni][par] + E[1][ni][par + 2]);
                s = bxsum(s, 4); s = bxsum(s, 8); s = bxsum(s, 16);
                civ[ni][par] = 1.0f / (32.0f * s);
            }
        // ---- w partial (over this warp's 16 cols) + rowmax: bfly over c4 (1,2)
        float w4[2][2], rm[2][2];
        #pragma unroll
        for (int mi = 0; mi < 2; mi++)
            #pragma unroll
            for (int eh = 0; eh < 2; eh++) {
                float wsum = E[mi][0][2 * eh] * civ[0][0] + E[mi][0][2 * eh + 1] * civ[0][1]
                           + E[mi][1][2 * eh] * civ[1][0] + E[mi][1][2 * eh + 1] * civ[1][1];
                wsum = bxsum(wsum, 1); wsum = bxsum(wsum, 2);
                w4[mi][eh] = wsum;
                float m = fmaxf(fmaxf(C[mi][0][2 * eh], C[mi][0][2 * eh + 1]),
                                fmaxf(C[mi][1][2 * eh], C[mi][1][2 * eh + 1]));
                m = bxmax(m, 1); m = bxmax(m, 2);
                rm[mi][eh] = m;
            }
        // ---- combine 1 across the two dh=1 warps (rowmax + w partials)
        if (c4 == 0) {
            #pragma unroll
            for (int mi = 0; mi < 2; mi++)
                #pragma unroll
                for (int eh = 0; eh < 2; eh++) {
                    const int row = 16 * mi + r8 + 8 * eh;
                    RM[nh * 32 + row]  = rm[mi][eh];
                    WPc[nh * 32 + row] = w4[mi][eh];
                }
        }
        asm volatile("bar.sync 1, 64;" ::: "memory");
        float Mr4[2][2], wt[2][2];
        #pragma unroll
        for (int mi = 0; mi < 2; mi++)
            #pragma unroll
            for (int eh = 0; eh < 2; eh++) {
                const int row = 16 * mi + r8 + 8 * eh;
                Mr4[mi][eh] = fmaxf(RM[row], RM[32 + row]);
                wt[mi][eh]  = WPc[row] + WPc[32 + row];
            }
        // ---- row-stabilized exps + rowsum partial
        #pragma unroll
        for (int mi = 0; mi < 2; mi++)
            #pragma unroll
            for (int ni = 0; ni < 2; ni++)
                #pragma unroll
                for (int e = 0; e < 4; e++)
                    E[mi][ni][e] = __expf(C[mi][ni][e] - Mr4[mi][e >> 1]);
        float rp[2][2];
        #pragma unroll
        for (int mi = 0; mi < 2; mi++)
            #pragma unroll
            for (int eh = 0; eh < 2; eh++) {
                float s = (E[mi][0][2 * eh] + E[mi][0][2 * eh + 1])
                        + (E[mi][1][2 * eh] + E[mi][1][2 * eh + 1]);
                s = bxsum(s, 1); s = bxsum(s, 2);
                rp[mi][eh] = s;
            }
        if (c4 == 0) {
            #pragma unroll
            for (int mi = 0; mi < 2; mi++)
                #pragma unroll
                for (int eh = 0; eh < 2; eh++)
                    RSc[nh * 32 + 16 * mi + r8 + 8 * eh] = rp[mi][eh];
        }
        asm volatile("bar.sync 1, 64;" ::: "memory");
        float p4[2][2];
        #pragma unroll
        for (int mi = 0; mi < 2; mi++)
            #pragma unroll
            for (int eh = 0; eh < 2; eh++) {
                const int row = 16 * mi + r8 + 8 * eh;
                p4[mi][eh] = __fdividef(wt[mi][eh], RSc[row] + RSc[32 + row]);
            }
        // ---- v[col] = sum_rows p * R : in-thread 4 rows + bfly over r8
        #pragma unroll
        for (int ni = 0; ni < 2; ni++)
            #pragma unroll
            for (int par = 0; par < 2; par++) {
                float s = p4[0][0] * E[0][ni][par]     + p4[0][1] * E[0][ni][par + 2]
                        + p4[1][0] * E[1][ni][par]     + p4[1][1] * E[1][ni][par + 2];
                s = bxsum(s, 4); s = bxsum(s, 8); s = bxsum(s, 16);
                if (r8 == 0)
                    Vv[16 * nh + 8 * ni + 2 * c4 + par] = s;
            }
        if (c4 == 0 && nh == 0) {
            #pragma unroll
            for (int mi = 0; mi < 2; mi++)
                #pragma unroll
                for (int eh = 0; eh < 2; eh++)
                    Wv[16 * mi + r8 + 8 * eh] = wt[mi][eh];
        }
    }
    __syncthreads();

    // ---- m = [mean_k Qm | w^T Dm | v^T Qm] (bank 4j+d, lanes distinct) ----
    {
        const int d = tid;
        float m1 = 0.f, m2 = 0.f, m3 = 0.f;
        #pragma unroll
        for (int j = 0; j < KN; j++) {
            float dd = DQ[j * RP + d];
            float qq = DQ[(32 + j) * RP + d];
            m1 += qq;
            m2 += Wv[j] * dd;
            m3 += Vv[j] * qq;
        }
        sm[d]       = m1 * (1.0f / 32.0f);
        sm[128 + d] = m2;
        sm[256 + d] = m3;
    }
    __syncthreads();

    // ---- AvgPool1d(3,3) + residual (prefetched) ----
    {
        const int g = tid;
        float h = (sm[3 * g] + sm[3 * g + 1] + sm[3 * g + 2]) * (1.0f / 3.0f);
        out[node * DF + g] = res + h;
    }
}

extern "C" void kernel_launch(void* const* d_in, const int* in_sizes, int n_in,
                              void* d_out, int out_size)
{
    const float* feat = (const float*)d_in[0];
    const int*   sim  = (const int*)d_in[1];
    const int*   cor  = (const int*)d_in[2];
    float*       out  = (float*)d_out;

    const int n_nodes = in_sizes[1] / KN;    // 20000
    cudaFuncSetAttribute(coatt_mma, cudaFuncAttributeMaxDynamicSharedMemorySize, SMEM_BYTES);
    coatt_mma<<<n_nodes, 128, SMEM_BYTES>>>(feat, sim, cor, out);
}